// round 16
// baseline (speedup 1.0000x reference)
#include <cuda_runtime.h>
#include <cuda_fp16.h>
#include <math.h>

#define NN 50000
#define EPS_BN 1e-5f
#define CSR_NBLK 49
#define EPA 900000

// ---------------- scratch (device globals: allocation-free) ----------------
static __device__ __half g_xh[(long long)NN * 128];
static __device__ __half g_w1h[128 * 256];
static __device__ __half g_w2h[256 * 128];
static __device__ __half g_h1h[(long long)NN * 256];
static __device__ __half g_out1h[(long long)NN * 256];
static __device__ __half g_h2h[(long long)NN * 128];
static __device__ float g_s1[NN * 4];
static __device__ float g_d1[NN * 4];
static __device__ float g_s2[NN * 4];
static __device__ float g_d2[NN * 4];
static __device__ float g_ex[4 * EPA];     // planar per-head edge weights
static __device__ int g_deg[NN];
static __device__ int g_cur[NN];
static __device__ int g_rowptr[NN + 1];
static __device__ int g_pflag[64];
static __device__ int g_col[EPA];
static __device__ int g_dstc[EPA];
static __device__ unsigned long long g_bar;

__device__ __forceinline__ float lrelu(float x) { return x > 0.f ? x : 0.2f * x; }

// ---------------- fused fp32 -> fp16 convert (x, W1, W2) ----------------
__global__ void __launch_bounds__(256) f2h_all_kernel(
    const float* __restrict__ x, const float* __restrict__ W1,
    const float* __restrict__ W2)
{
    const int n4x = NN * 128 / 4;
    const int n4w = 128 * 256 / 4;
    int i = blockIdx.x * 256 + threadIdx.x;
    const float* src;
    __half* dst;
    int li;
    if (i < n4x) { src = x; dst = g_xh; li = i; }
    else if (i < n4x + n4w) { src = W1; dst = g_w1h; li = i - n4x; }
    else if (i < n4x + 2 * n4w) { src = W2; dst = g_w2h; li = i - n4x - n4w; }
    else return;
    float4 v = ((const float4*)src)[li];
    __half2 h0 = __float22half2_rn(make_float2(v.x, v.y));
    __half2 h1 = __float22half2_rn(make_float2(v.z, v.w));
    uint2 w;
    w.x = *(unsigned int*)&h0; w.y = *(unsigned int*)&h1;
    ((uint2*)dst)[li] = w;
}

// ---------------- grid barrier (monotonic tickets: replay-safe) -------------
__device__ __forceinline__ void grid_barrier() {
    __syncthreads();
    if (threadIdx.x == 0) {
        __threadfence();
        unsigned long long tk = atomicAdd(&g_bar, 1ULL);
        unsigned long long target = (tk / CSR_NBLK + 1ULL) * (unsigned long long)CSR_NBLK;
        unsigned long long v;
        do {
            asm volatile("ld.volatile.global.u64 %0, [%1];" : "=l"(v) : "l"(&g_bar));
        } while (v < target);
        __threadfence();
    }
    __syncthreads();
}

// ---------------- fused CSR build: zero + detect + count + scan + scatter ---
__global__ void __launch_bounds__(1024) csr_kernel(
    const void* __restrict__ e, int E, int EP)
{
    __shared__ int sh[1024];
    __shared__ int s_prefix;
    __shared__ int s_is64;
    int t = threadIdx.x, b = blockIdx.x;
    int gtid = b * 1024 + t;
    const int nthr = CSR_NBLK * 1024;
    const int* e32 = (const int*)e;
    const long long* e64 = (const long long*)e;

    if (gtid < NN) { g_deg[gtid] = 0; g_cur[gtid] = 0; }
    if (gtid < 64) g_pflag[gtid] = 0;
    if (t == 0) s_is64 = 1;
    __syncthreads();
    if (t < 256 && e32[2 * t + 1] != 0) s_is64 = 0;
    __syncthreads();
    int is64 = s_is64;
    grid_barrier();

    for (int i = gtid; i < EP; i += nthr) {
        int d = (i < E) ? (is64 ? (int)e64[(long long)E + i] : e32[E + i]) : (i - E);
        atomicAdd(&g_deg[d], 1);
    }
    grid_barrier();

    {
        int i = gtid;
        int v = (i < NN) ? g_deg[i] : 0;
        sh[t] = v;
        __syncthreads();
#pragma unroll
        for (int off = 1; off < 1024; off <<= 1) {
            int tv = (t >= off) ? sh[t - off] : 0;
            __syncthreads();
            sh[t] += tv;
            __syncthreads();
        }
        int total = sh[1023];
        if (t == 1023) {
            __threadfence();
            atomicExch(&g_pflag[b], total + 1);
        }
        if (t < 32) {
            int sum = 0;
            for (int p = t; p < b; p += 32) {
                int w;
                do { w = atomicAdd(&g_pflag[p], 0); } while (w == 0);
                sum += w - 1;
            }
#pragma unroll
            for (int off = 16; off; off >>= 1) sum += __shfl_xor_sync(0xffffffffu, sum, off);
            if (t == 0) s_prefix = sum;
        }
        __syncthreads();
        if (i < NN) g_rowptr[i] = s_prefix + sh[t] - v;
        if (b == CSR_NBLK - 1 && t == 1023) g_rowptr[NN] = s_prefix + total;
    }
    grid_barrier();

    for (int i = gtid; i < EP; i += nthr) {
        int s, d;
        if (i < E) {
            if (is64) { s = (int)e64[i]; d = (int)e64[(long long)E + i]; }
            else      { s = e32[i];      d = e32[E + i]; }
        } else { s = i - E; d = s; }
        int pos = atomicAdd(&g_cur[d], 1);
        int slot = g_rowptr[d] + pos;
        g_col[slot] = s;
        g_dstc[slot] = d;
    }
}

// ---------------- edge-weight precompute: ex[h][j] = exp(lrelu(s+d)) --------
__global__ void __launch_bounds__(256) ex_kernel(
    const float* __restrict__ sArr, const float* __restrict__ dArr, int EP)
{
    int i = blockIdx.x * 256 + threadIdx.x;
    if (i >= EP) return;
    int s = g_col[i], d = g_dstc[i];
    float4 sv = *(const float4*)(sArr + 4 * s);
    float4 dv = *(const float4*)(dArr + 4 * d);
    g_ex[0 * EPA + i] = __expf(lrelu(sv.x + dv.x));
    g_ex[1 * EPA + i] = __expf(lrelu(sv.y + dv.y));
    g_ex[2 * EPA + i] = __expf(lrelu(sv.z + dv.z));
    g_ex[3 * EPA + i] = __expf(lrelu(sv.w + dv.w));
}

// ---------------- MMA / LDSM / cp.async helpers ----------------
__device__ __forceinline__ void mma_f16(
    float* c, unsigned int a0, unsigned int a1, unsigned int a2, unsigned int a3,
    unsigned int b0, unsigned int b1)
{
    asm("mma.sync.aligned.m16n8k16.row.col.f32.f16.f16.f32 "
        "{%0,%1,%2,%3}, {%4,%5,%6,%7}, {%8,%9}, {%0,%1,%2,%3};"
        : "+f"(c[0]), "+f"(c[1]), "+f"(c[2]), "+f"(c[3])
        : "r"(a0), "r"(a1), "r"(a2), "r"(a3), "r"(b0), "r"(b1));
}

__device__ __forceinline__ void ldsm_x4(
    unsigned int& d0, unsigned int& d1, unsigned int& d2, unsigned int& d3,
    unsigned int addr)
{
    asm volatile("ldmatrix.sync.aligned.m8n8.x4.shared.b16 {%0,%1,%2,%3}, [%4];"
        : "=r"(d0), "=r"(d1), "=r"(d2), "=r"(d3) : "r"(addr));
}

__device__ __forceinline__ void ldsm_x4_trans(
    unsigned int& d0, unsigned int& d1, unsigned int& d2, unsigned int& d3,
    unsigned int addr)
{
    asm volatile("ldmatrix.sync.aligned.m8n8.x4.trans.shared.b16 {%0,%1,%2,%3}, [%4];"
        : "=r"(d0), "=r"(d1), "=r"(d2), "=r"(d3) : "r"(addr));
}

__device__ __forceinline__ void cp_async16(unsigned int dst, const void* src) {
    asm volatile("cp.async.cg.shared.global [%0], [%1], 16;" :: "r"(dst), "l"(src));
}

// ---------------- GEMM (fp16 HMMA, 3-stage cp.async pipeline) ----------------
#define AS_STAGE (128 * 40)
#define BS_STAGE (32 * 136)
__global__ void __launch_bounds__(256, 2) gemm_kernel(
    const __half* __restrict__ A, const __half* __restrict__ B,
    __half* __restrict__ Ch,
    const float* __restrict__ as, const float* __restrict__ ad,
    float* __restrict__ sOut, float* __restrict__ dOut,
    int M, int K, int Nc, int cpl2)
{
    extern __shared__ __half dsm[];
    __half (*As)[128][40] = (__half(*)[128][40])dsm;
    __half (*Bs)[32][136] = (__half(*)[32][136])(dsm + 3 * AS_STAGE);
    float* sm_s = (float*)(dsm + 3 * AS_STAGE + 3 * BS_STAGE);
    float* sm_d = sm_s + 512;

    int tid = threadIdx.x;
    int lane = tid & 31;
    int w = tid >> 5;
    int wm = (w & 1) * 64;
    int wn = (w >> 1) * 32;
    int lr = lane >> 2;
    int lc = lane & 3;
    int row0 = blockIdx.y * 128;
    int col0 = blockIdx.x * 128;

    for (int q = tid; q < 1024; q += 256) sm_s[q] = 0.f;

    float c[4][4][4];
#pragma unroll
    for (int i = 0; i < 4; i++)
#pragma unroll
        for (int j = 0; j < 4; j++)
#pragma unroll
            for (int r = 0; r < 4; r++) c[i][j][r] = 0.f;

    auto stage = [&](int k0, int b) {
#pragma unroll
        for (int s0 = 0; s0 < 2; s0++) {
            int cidx = tid + s0 * 256;
            int r = cidx >> 2;
            int ko = (cidx & 3) << 3;
            long long gr = row0 + r;
            if (gr >= M) gr = M - 1;
            cp_async16((unsigned int)__cvta_generic_to_shared(&As[b][r][ko]),
                       A + gr * K + k0 + ko);
        }
#pragma unroll
        for (int s0 = 0; s0 < 2; s0++) {
            int cidx = tid + s0 * 256;
            int kr = cidx >> 4;
            int no = (cidx & 15) << 3;
            cp_async16((unsigned int)__cvta_generic_to_shared(&Bs[b][kr][no]),
                       B + (long long)(k0 + kr) * Nc + col0 + no);
        }
        asm volatile("cp.async.commit_group;");
    };

    int nchunk = K >> 5;
    stage(0, 0);
    if (nchunk > 1) stage(32, 1);

    for (int ch = 0; ch < nchunk; ch++) {
        int buf = ch % 3;
        if (ch < nchunk - 1) {
            asm volatile("cp.async.wait_group 1;" ::: "memory");
        } else {
            asm volatile("cp.async.wait_group 0;" ::: "memory");
        }
        __syncthreads();
        if (ch + 2 < nchunk) stage((ch + 2) << 5, (ch + 2) % 3);

#pragma unroll
        for (int ks2 = 0; ks2 < 2; ks2++) {
            int ks = ks2 * 16;
            unsigned int bf[4][2];
#pragma unroll
            for (int np = 0; np < 2; np++) {
                int bn = wn + np * 16 + (lane >> 4) * 8;
                unsigned int addr = (unsigned int)__cvta_generic_to_shared(
                    &Bs[buf][(lane & 15) + ks][bn]);
                unsigned int d0, d1, d2, d3;
                ldsm_x4_trans(d0, d1, d2, d3, addr);
                bf[2 * np][0] = d0;     bf[2 * np][1] = d1;
                bf[2 * np + 1][0] = d2; bf[2 * np + 1][1] = d3;
            }
#pragma unroll
            for (int mf = 0; mf < 4; mf++) {
                int arow = wm + (lane & 15) + mf * 16;
                int akoff = (lane >> 4) * 8 + ks;
                unsigned int addr = (unsigned int)__cvta_generic_to_shared(
                    &As[buf][arow][akoff]);
                unsigned int a0, a1, a2, a3;
                ldsm_x4(a0, a1, a2, a3, addr);
#pragma unroll
                for (int nf = 0; nf < 4; nf++)
                    mma_f16(c[mf][nf], a0, a1, a2, a3, bf[nf][0], bf[nf][1]);
            }
        }
    }
    __syncthreads();

    int hlw = wn >> cpl2;
    float av[4][2], dv[4][2];
#pragma unroll
    for (int nf = 0; nf < 4; nf++) {
#pragma unroll
        for (int e = 0; e < 2; e++) {
            int cg = col0 + wn + nf * 8 + lc * 2 + e;
            av[nf][e] = as[cg];
            dv[nf][e] = ad[cg];
        }
    }
#pragma unroll
    for (int mf = 0; mf < 4; mf++) {
#pragma unroll
        for (int rs = 0; rs < 2; rs++) {
            int row = wm + mf * 16 + lr + rs * 8;
            int gr = row0 + row;
            if (gr < M) {
                float ps = 0.f, pd = 0.f;
#pragma unroll
                for (int nf = 0; nf < 4; nf++) {
                    float o0 = c[mf][nf][rs * 2 + 0];
                    float o1 = c[mf][nf][rs * 2 + 1];
                    ps += o0 * av[nf][0] + o1 * av[nf][1];
                    pd += o0 * dv[nf][0] + o1 * dv[nf][1];
                    __half2 hp = __float22half2_rn(make_float2(o0, o1));
                    *(__half2*)(Ch + (long long)gr * Nc + col0 + wn + nf * 8 + lc * 2) = hp;
                }
                atomicAdd(&sm_s[row * 4 + hlw], ps);
                atomicAdd(&sm_d[row * 4 + hlw], pd);
            }
        }
    }
    __syncthreads();
    int hpb = 128 >> cpl2;
    int hb  = col0 >> cpl2;
    for (int q = tid; q < 128 * hpb; q += 256) {
        int r = q / hpb, hh = q % hpb;
        int gr = row0 + r;
        if (gr < M) {
            sOut[4 * gr + hb + hh] = sm_s[r * 4 + hh];
            dOut[4 * gr + hb + hh] = sm_d[r * 4 + hh];
        }
    }
}

__device__ __forceinline__ void acc8_fp16(float* acc, uint4 v, float ex) {
    float2 f0 = __half22float2(*(__half2*)&v.x);
    float2 f1 = __half22float2(*(__half2*)&v.y);
    float2 f2 = __half22float2(*(__half2*)&v.z);
    float2 f3 = __half22float2(*(__half2*)&v.w);
    acc[0] += ex * f0.x; acc[1] += ex * f0.y;
    acc[2] += ex * f1.x; acc[3] += ex * f1.y;
    acc[4] += ex * f2.x; acc[5] += ex * f2.y;
    acc[6] += ex * f3.x; acc[7] += ex * f3.y;
}

// ---------------- GAT aggregation layer 1 (precomputed ex) ------------------
__global__ void __launch_bounds__(256) agg1_kernel(
    const float* __restrict__ b1, const float* __restrict__ gm,
    const float* __restrict__ bt, const float* __restrict__ mn,
    const float* __restrict__ vr)
{
    int gw = (blockIdx.x * blockDim.x + threadIdx.x) >> 5;
    if (gw >= NN) return;
    int l = threadIdx.x & 31;
    int start = g_rowptr[gw], end = g_rowptr[gw + 1];
    int head = l >> 3;
    const float* exh = g_ex + head * EPA;
    int c0 = l << 3;
    float acc[8] = {0.f, 0.f, 0.f, 0.f, 0.f, 0.f, 0.f, 0.f};
    float den = 0.f;

    int j = start;
    for (; j + 4 <= end; j += 4) {
        int s0 = g_col[j], s1 = g_col[j + 1], s2 = g_col[j + 2], s3 = g_col[j + 3];
        float e0 = exh[j], e1 = exh[j + 1], e2 = exh[j + 2], e3 = exh[j + 3];
        uint4 v0 = *(const uint4*)(g_h1h + (long long)s0 * 256 + c0);
        uint4 v1 = *(const uint4*)(g_h1h + (long long)s1 * 256 + c0);
        uint4 v2 = *(const uint4*)(g_h1h + (long long)s2 * 256 + c0);
        uint4 v3 = *(const uint4*)(g_h1h + (long long)s3 * 256 + c0);
        den += (e0 + e1) + (e2 + e3);
        acc8_fp16(acc, v0, e0);
        acc8_fp16(acc, v1, e1);
        acc8_fp16(acc, v2, e2);
        acc8_fp16(acc, v3, e3);
    }
    for (; j < end; j++) {
        int s = g_col[j];
        float ex = exh[j];
        den += ex;
        uint4 v = *(const uint4*)(g_h1h + (long long)s * 256 + c0);
        acc8_fp16(acc, v, ex);
    }
    float inv = 1.f / (den + 1e-16f);
    float out[8];
#pragma unroll
    for (int i = 0; i < 8; i++) {
        int cc = c0 + i;
        float v = acc[i] * inv + b1[cc];
        v = (v - mn[cc]) * rsqrtf(vr[cc] + EPS_BN) * gm[cc] + bt[cc];
        out[i] = v > 0.f ? v : expm1f(v);
    }
    __half2 q0 = __float22half2_rn(make_float2(out[0], out[1]));
    __half2 q1 = __float22half2_rn(make_float2(out[2], out[3]));
    __half2 q2 = __float22half2_rn(make_float2(out[4], out[5]));
    __half2 q3 = __float22half2_rn(make_float2(out[6], out[7]));
    uint4 wv;
    wv.x = *(unsigned int*)&q0; wv.y = *(unsigned int*)&q1;
    wv.z = *(unsigned int*)&q2; wv.w = *(unsigned int*)&q3;
    *(uint4*)(g_out1h + (long long)gw * 256 + c0) = wv;
}

// ------------ GAT aggregation layer 2 (precomputed ex, BN+ELU+FC) -----------
__global__ void __launch_bounds__(256) agg2_kernel(
    const float* __restrict__ b2, const float* __restrict__ gm,
    const float* __restrict__ bt, const float* __restrict__ mn,
    const float* __restrict__ vr, const float* __restrict__ fcW,
    const float* __restrict__ fcb, float* __restrict__ out)
{
    int gw = (blockIdx.x * blockDim.x + threadIdx.x) >> 5;
    if (gw >= NN) return;
    int l = threadIdx.x & 31;
    int start = g_rowptr[gw], end = g_rowptr[gw + 1];
    int head = l >> 3;
    const float* exh = g_ex + head * EPA;
    int c0 = l << 2;
    float acc[4] = {0.f, 0.f, 0.f, 0.f};
    float den = 0.f;

    int j = start;
    for (; j + 4 <= end; j += 4) {
        int s0 = g_col[j], s1 = g_col[j + 1], s2 = g_col[j + 2], s3 = g_col[j + 3];
        float e0 = exh[j], e1 = exh[j + 1], e2 = exh[j + 2], e3 = exh[j + 3];
        uint2 v0 = *(const uint2*)(g_h2h + (long long)s0 * 128 + c0);
        uint2 v1 = *(const uint2*)(g_h2h + (long long)s1 * 128 + c0);
        uint2 v2 = *(const uint2*)(g_h2h + (long long)s2 * 128 + c0);
        uint2 v3 = *(const uint2*)(g_h2h + (long long)s3 * 128 + c0);
        den += (e0 + e1) + (e2 + e3);
        float2 f;
        f = __half22float2(*(__half2*)&v0.x); acc[0] += e0*f.x; acc[1] += e0*f.y;
        f = __half22float2(*(__half2*)&v0.y); acc[2] += e0*f.x; acc[3] += e0*f.y;
        f = __half22float2(*(__half2*)&v1.x); acc[0] += e1*f.x; acc[1] += e1*f.y;
        f = __half22float2(*(__half2*)&v1.y); acc[2] += e1*f.x; acc[3] += e1*f.y;
        f = __half22float2(*(__half2*)&v2.x); acc[0] += e2*f.x; acc[1] += e2*f.y;
        f = __half22float2(*(__half2*)&v2.y); acc[2] += e2*f.x; acc[3] += e2*f.y;
        f = __half22float2(*(__half2*)&v3.x); acc[0] += e3*f.x; acc[1] += e3*f.y;
        f = __half22float2(*(__half2*)&v3.y); acc[2] += e3*f.x; acc[3] += e3*f.y;
    }
    for (; j < end; j++) {
        int s = g_col[j];
        float ex = exh[j];
        den += ex;
        uint2 v0 = *(const uint2*)(g_h2h + (long long)s * 128 + c0);
        float2 f;
        f = __half22float2(*(__half2*)&v0.x); acc[0] += ex*f.x; acc[1] += ex*f.y;
        f = __half22float2(*(__half2*)&v0.y); acc[2] += ex*f.x; acc[3] += ex*f.y;
    }
    float inv = 1.f / (den + 1e-16f);
    float r = 0.f;
#pragma unroll
    for (int i = 0; i < 4; i++) {
        int cc = c0 + i;
        float v = acc[i] * inv + b2[cc];
        v = (v - mn[cc]) * rsqrtf(vr[cc] + EPS_BN) * gm[cc] + bt[cc];
        v = v > 0.f ? v : expm1f(v);
        r += v * fcW[cc];
    }
#pragma unroll
    for (int off = 16; off; off >>= 1) r += __shfl_xor_sync(0xffffffffu, r, off);
    if (l == 0) out[gw] = r + fcb[0];
}

// ---------------- launch ----------------
extern "C" void kernel_launch(void* const* d_in, const int* in_sizes, int n_in,
                              void* d_out, int out_size) {
    const float* x    = (const float*)d_in[0];
    const void*  eidx = d_in[1];
    const float* W1   = (const float*)d_in[2];
    const float* a1s  = (const float*)d_in[3];
    const float* a1d  = (const float*)d_in[4];
    const float* b1   = (const float*)d_in[5];
    const float* g1   = (const float*)d_in[6];
    const float* be1  = (const float*)d_in[7];
    const float* m1   = (const float*)d_in[8];
    const float* v1   = (const float*)d_in[9];
    const float* W2   = (const float*)d_in[10];
    const float* a2s  = (const float*)d_in[11];
    const float* a2d  = (const float*)d_in[12];
    const float* b2   = (const float*)d_in[13];
    const float* g2   = (const float*)d_in[14];
    const float* be2  = (const float*)d_in[15];
    const float* m2   = (const float*)d_in[16];
    const float* v2   = (const float*)d_in[17];
    const float* fcW  = (const float*)d_in[18];
    const float* fcb  = (const float*)d_in[19];

    int E  = in_sizes[1] / 2;
    int EP = E + NN;

    int smem_bytes = (3 * AS_STAGE + 3 * BS_STAGE) * 2 + 1024 * 4;
    cudaFuncSetAttribute(gemm_kernel,
        cudaFuncAttributeMaxDynamicSharedMemorySize, smem_bytes);
    cudaFuncSetAttribute(gemm_kernel,
        cudaFuncAttributePreferredSharedMemoryCarveout, 100);

    static cudaStream_t s_side = 0;
    static cudaEvent_t  s_fork = 0, s_join = 0;
    if (!s_side) {
        cudaStreamCreateWithFlags(&s_side, cudaStreamNonBlocking);
        cudaEventCreateWithFlags(&s_fork, cudaEventDisableTiming);
        cudaEventCreateWithFlags(&s_join, cudaEventDisableTiming);
    }

    float *s1p, *d1p, *s2p, *d2p;
    __half *h1hp, *h2hp, *out1hp, *xhp, *w1hp, *w2hp;
    cudaGetSymbolAddress((void**)&h1hp,   g_h1h);
    cudaGetSymbolAddress((void**)&h2hp,   g_h2h);
    cudaGetSymbolAddress((void**)&out1hp, g_out1h);
    cudaGetSymbolAddress((void**)&xhp,    g_xh);
    cudaGetSymbolAddress((void**)&w1hp,   g_w1h);
    cudaGetSymbolAddress((void**)&w2hp,   g_w2h);
    cudaGetSymbolAddress((void**)&s1p,    g_s1);
    cudaGetSymbolAddress((void**)&d1p,    g_d1);
    cudaGetSymbolAddress((void**)&s2p,    g_s2);
    cudaGetSymbolAddress((void**)&d2p,    g_d2);

    const int TPB = 256;
    int warp_blocks = (NN * 32 + TPB - 1) / TPB;
    int edge_blocks = (EP + TPB - 1) / TPB;
    int f2h_blocks  = (NN * 128 / 4 + 2 * (128 * 256 / 4) + 255) / 256;

    // fork: CSR build (side) concurrent with f2h+gemm1 (main)
    cudaEventRecord(s_fork, 0);
    cudaStreamWaitEvent(s_side, s_fork, 0);
    csr_kernel<<<CSR_NBLK, 1024, 0, s_side>>>(eidx, E, EP);
    cudaEventRecord(s_join, s_side);

    f2h_all_kernel<<<f2h_blocks, 256>>>(x, W1, W2);
    gemm_kernel<<<dim3(2, (NN + 127) / 128), 256, smem_bytes>>>(
        xhp, w1hp, h1hp, a1s, a1d, s1p, d1p, NN, 128, 256, 6);

    // layer 1: ex precompute (needs CSR + gemm1), then agg1
    cudaStreamWaitEvent(0, s_join, 0);
    ex_kernel<<<edge_blocks, TPB>>>(s1p, d1p, EP);
    agg1_kernel<<<warp_blocks, TPB>>>(b1, g1, be1, m1, v1);

    // layer 2
    gemm_kernel<<<dim3(1, (NN + 127) / 128), 256, smem_bytes>>>(
        out1hp, w2hp, h2hp, a2s, a2d, s2p, d2p, NN, 256, 128, 5);
    ex_kernel<<<edge_blocks, TPB>>>(s2p, d2p, EP);
    agg2_kernel<<<warp_blocks, TPB>>>(b2, g2, be2, m2, v2, fcW, fcb, (float*)d_out);
}

// round 17
// speedup vs baseline: 1.0973x; 1.0973x over previous
#include <cuda_runtime.h>
#include <cuda_fp16.h>
#include <math.h>

#define NN 50000
#define EPS_BN 1e-5f
#define CSR_NBLK 49

// ---------------- scratch (device globals: allocation-free) ----------------
static __device__ __half g_xh[(long long)NN * 128];
static __device__ __half g_w1h[128 * 256];
static __device__ __half g_w2h[256 * 128];
static __device__ __half g_h1h[(long long)NN * 256];
static __device__ __half g_out1h[(long long)NN * 256];
static __device__ __half g_h2h[(long long)NN * 128];
static __device__ float g_s1[NN * 4];
static __device__ float g_d1[NN * 4];
static __device__ float g_s2[NN * 4];
static __device__ float g_d2[NN * 4];
static __device__ int g_deg[NN];
static __device__ int g_cur[NN];
static __device__ int g_rowptr[NN + 1];
static __device__ int g_pflag[64];
static __device__ int g_col[900000];
static __device__ unsigned long long g_bar;

__device__ __forceinline__ float lrelu(float x) { return x > 0.f ? x : 0.2f * x; }

// ---------------- fused fp32 -> fp16 convert (x, W1, W2) ----------------
__global__ void __launch_bounds__(256) f2h_all_kernel(
    const float* __restrict__ x, const float* __restrict__ W1,
    const float* __restrict__ W2)
{
    const int n4x = NN * 128 / 4;
    const int n4w = 128 * 256 / 4;
    int i = blockIdx.x * 256 + threadIdx.x;
    const float* src;
    __half* dst;
    int li;
    if (i < n4x) { src = x; dst = g_xh; li = i; }
    else if (i < n4x + n4w) { src = W1; dst = g_w1h; li = i - n4x; }
    else if (i < n4x + 2 * n4w) { src = W2; dst = g_w2h; li = i - n4x - n4w; }
    else return;
    float4 v = ((const float4*)src)[li];
    __half2 h0 = __float22half2_rn(make_float2(v.x, v.y));
    __half2 h1 = __float22half2_rn(make_float2(v.z, v.w));
    uint2 w;
    w.x = *(unsigned int*)&h0; w.y = *(unsigned int*)&h1;
    ((uint2*)dst)[li] = w;
}

// ---------------- grid barrier (monotonic tickets: replay-safe) -------------
__device__ __forceinline__ void grid_barrier() {
    __syncthreads();
    if (threadIdx.x == 0) {
        __threadfence();
        unsigned long long tk = atomicAdd(&g_bar, 1ULL);
        unsigned long long target = (tk / CSR_NBLK + 1ULL) * (unsigned long long)CSR_NBLK;
        unsigned long long v;
        do {
            asm volatile("ld.volatile.global.u64 %0, [%1];" : "=l"(v) : "l"(&g_bar));
        } while (v < target);
        __threadfence();
    }
    __syncthreads();
}

// ---------------- fused CSR build: zero + detect + count + scan + scatter ---
__global__ void __launch_bounds__(1024) csr_kernel(
    const void* __restrict__ e, int E, int EP)
{
    __shared__ int sh[1024];
    __shared__ int s_prefix;
    __shared__ int s_is64;
    int t = threadIdx.x, b = blockIdx.x;
    int gtid = b * 1024 + t;
    const int nthr = CSR_NBLK * 1024;
    const int* e32 = (const int*)e;
    const long long* e64 = (const long long*)e;

    if (gtid < NN) { g_deg[gtid] = 0; g_cur[gtid] = 0; }
    if (gtid < 64) g_pflag[gtid] = 0;
    if (t == 0) s_is64 = 1;
    __syncthreads();
    if (t < 256 && e32[2 * t + 1] != 0) s_is64 = 0;
    __syncthreads();
    int is64 = s_is64;
    grid_barrier();

    for (int i = gtid; i < EP; i += nthr) {
        int d = (i < E) ? (is64 ? (int)e64[(long long)E + i] : e32[E + i]) : (i - E);
        atomicAdd(&g_deg[d], 1);
    }
    grid_barrier();

    {
        int i = gtid;
        int v = (i < NN) ? g_deg[i] : 0;
        sh[t] = v;
        __syncthreads();
#pragma unroll
        for (int off = 1; off < 1024; off <<= 1) {
            int tv = (t >= off) ? sh[t - off] : 0;
            __syncthreads();
            sh[t] += tv;
            __syncthreads();
        }
        int total = sh[1023];
        if (t == 1023) {
            __threadfence();
            atomicExch(&g_pflag[b], total + 1);
        }
        if (t < 32) {
            int sum = 0;
            for (int p = t; p < b; p += 32) {
                int w;
                do { w = atomicAdd(&g_pflag[p], 0); } while (w == 0);
                sum += w - 1;
            }
#pragma unroll
            for (int off = 16; off; off >>= 1) sum += __shfl_xor_sync(0xffffffffu, sum, off);
            if (t == 0) s_prefix = sum;
        }
        __syncthreads();
        if (i < NN) g_rowptr[i] = s_prefix + sh[t] - v;
        if (b == CSR_NBLK - 1 && t == 1023) g_rowptr[NN] = s_prefix + total;
    }
    grid_barrier();

    for (int i = gtid; i < EP; i += nthr) {
        int s, d;
        if (i < E) {
            if (is64) { s = (int)e64[i]; d = (int)e64[(long long)E + i]; }
            else      { s = e32[i];      d = e32[E + i]; }
        } else { s = i - E; d = s; }
        int pos = atomicAdd(&g_cur[d], 1);
        g_col[g_rowptr[d] + pos] = s;
    }
}

// ---------------- MMA / LDSM / cp.async helpers ----------------
__device__ __forceinline__ void mma_f16(
    float* c, unsigned int a0, unsigned int a1, unsigned int a2, unsigned int a3,
    unsigned int b0, unsigned int b1)
{
    asm("mma.sync.aligned.m16n8k16.row.col.f32.f16.f16.f32 "
        "{%0,%1,%2,%3}, {%4,%5,%6,%7}, {%8,%9}, {%0,%1,%2,%3};"
        : "+f"(c[0]), "+f"(c[1]), "+f"(c[2]), "+f"(c[3])
        : "r"(a0), "r"(a1), "r"(a2), "r"(a3), "r"(b0), "r"(b1));
}

__device__ __forceinline__ void ldsm_x4(
    unsigned int& d0, unsigned int& d1, unsigned int& d2, unsigned int& d3,
    unsigned int addr)
{
    asm volatile("ldmatrix.sync.aligned.m8n8.x4.shared.b16 {%0,%1,%2,%3}, [%4];"
        : "=r"(d0), "=r"(d1), "=r"(d2), "=r"(d3) : "r"(addr));
}

__device__ __forceinline__ void ldsm_x4_trans(
    unsigned int& d0, unsigned int& d1, unsigned int& d2, unsigned int& d3,
    unsigned int addr)
{
    asm volatile("ldmatrix.sync.aligned.m8n8.x4.trans.shared.b16 {%0,%1,%2,%3}, [%4];"
        : "=r"(d0), "=r"(d1), "=r"(d2), "=r"(d3) : "r"(addr));
}

__device__ __forceinline__ void cp_async16(unsigned int dst, const void* src) {
    asm volatile("cp.async.cg.shared.global [%0], [%1], 16;" :: "r"(dst), "l"(src));
}

// ---------------- GEMM (fp16 HMMA, 3-stage cp.async pipeline) ----------------
#define AS_STAGE (128 * 40)
#define BS_STAGE (32 * 136)
__global__ void __launch_bounds__(256, 2) gemm_kernel(
    const __half* __restrict__ A, const __half* __restrict__ B,
    __half* __restrict__ Ch,
    const float* __restrict__ as, const float* __restrict__ ad,
    float* __restrict__ sOut, float* __restrict__ dOut,
    int M, int K, int Nc, int cpl2)
{
    extern __shared__ __half dsm[];
    __half (*As)[128][40] = (__half(*)[128][40])dsm;
    __half (*Bs)[32][136] = (__half(*)[32][136])(dsm + 3 * AS_STAGE);
    float* sm_s = (float*)(dsm + 3 * AS_STAGE + 3 * BS_STAGE);
    float* sm_d = sm_s + 512;

    int tid = threadIdx.x;
    int lane = tid & 31;
    int w = tid >> 5;
    int wm = (w & 1) * 64;
    int wn = (w >> 1) * 32;
    int lr = lane >> 2;
    int lc = lane & 3;
    int row0 = blockIdx.y * 128;
    int col0 = blockIdx.x * 128;

    for (int q = tid; q < 1024; q += 256) sm_s[q] = 0.f;

    float c[4][4][4];
#pragma unroll
    for (int i = 0; i < 4; i++)
#pragma unroll
        for (int j = 0; j < 4; j++)
#pragma unroll
            for (int r = 0; r < 4; r++) c[i][j][r] = 0.f;

    auto stage = [&](int k0, int b) {
#pragma unroll
        for (int s0 = 0; s0 < 2; s0++) {
            int cidx = tid + s0 * 256;
            int r = cidx >> 2;
            int ko = (cidx & 3) << 3;
            long long gr = row0 + r;
            if (gr >= M) gr = M - 1;
            cp_async16((unsigned int)__cvta_generic_to_shared(&As[b][r][ko]),
                       A + gr * K + k0 + ko);
        }
#pragma unroll
        for (int s0 = 0; s0 < 2; s0++) {
            int cidx = tid + s0 * 256;
            int kr = cidx >> 4;
            int no = (cidx & 15) << 3;
            cp_async16((unsigned int)__cvta_generic_to_shared(&Bs[b][kr][no]),
                       B + (long long)(k0 + kr) * Nc + col0 + no);
        }
        asm volatile("cp.async.commit_group;");
    };

    int nchunk = K >> 5;
    stage(0, 0);
    if (nchunk > 1) stage(32, 1);

    for (int ch = 0; ch < nchunk; ch++) {
        int buf = ch % 3;
        if (ch < nchunk - 1) {
            asm volatile("cp.async.wait_group 1;" ::: "memory");
        } else {
            asm volatile("cp.async.wait_group 0;" ::: "memory");
        }
        __syncthreads();
        if (ch + 2 < nchunk) stage((ch + 2) << 5, (ch + 2) % 3);

#pragma unroll
        for (int ks2 = 0; ks2 < 2; ks2++) {
            int ks = ks2 * 16;
            unsigned int bf[4][2];
#pragma unroll
            for (int np = 0; np < 2; np++) {
                int bn = wn + np * 16 + (lane >> 4) * 8;
                unsigned int addr = (unsigned int)__cvta_generic_to_shared(
                    &Bs[buf][(lane & 15) + ks][bn]);
                unsigned int d0, d1, d2, d3;
                ldsm_x4_trans(d0, d1, d2, d3, addr);
                bf[2 * np][0] = d0;     bf[2 * np][1] = d1;
                bf[2 * np + 1][0] = d2; bf[2 * np + 1][1] = d3;
            }
#pragma unroll
            for (int mf = 0; mf < 4; mf++) {
                int arow = wm + (lane & 15) + mf * 16;
                int akoff = (lane >> 4) * 8 + ks;
                unsigned int addr = (unsigned int)__cvta_generic_to_shared(
                    &As[buf][arow][akoff]);
                unsigned int a0, a1, a2, a3;
                ldsm_x4(a0, a1, a2, a3, addr);
#pragma unroll
                for (int nf = 0; nf < 4; nf++)
                    mma_f16(c[mf][nf], a0, a1, a2, a3, bf[nf][0], bf[nf][1]);
            }
        }
    }
    __syncthreads();

    int hlw = wn >> cpl2;
    float av[4][2], dv[4][2];
#pragma unroll
    for (int nf = 0; nf < 4; nf++) {
#pragma unroll
        for (int e = 0; e < 2; e++) {
            int cg = col0 + wn + nf * 8 + lc * 2 + e;
            av[nf][e] = as[cg];
            dv[nf][e] = ad[cg];
        }
    }
#pragma unroll
    for (int mf = 0; mf < 4; mf++) {
#pragma unroll
        for (int rs = 0; rs < 2; rs++) {
            int row = wm + mf * 16 + lr + rs * 8;
            int gr = row0 + row;
            if (gr < M) {
                float ps = 0.f, pd = 0.f;
#pragma unroll
                for (int nf = 0; nf < 4; nf++) {
                    float o0 = c[mf][nf][rs * 2 + 0];
                    float o1 = c[mf][nf][rs * 2 + 1];
                    ps += o0 * av[nf][0] + o1 * av[nf][1];
                    pd += o0 * dv[nf][0] + o1 * dv[nf][1];
                    __half2 hp = __float22half2_rn(make_float2(o0, o1));
                    *(__half2*)(Ch + (long long)gr * Nc + col0 + wn + nf * 8 + lc * 2) = hp;
                }
                atomicAdd(&sm_s[row * 4 + hlw], ps);
                atomicAdd(&sm_d[row * 4 + hlw], pd);
            }
        }
    }
    __syncthreads();
    int hpb = 128 >> cpl2;
    int hb  = col0 >> cpl2;
    for (int q = tid; q < 128 * hpb; q += 256) {
        int r = q / hpb, hh = q % hpb;
        int gr = row0 + r;
        if (gr < M) {
            sOut[4 * gr + hb + hh] = sm_s[r * 4 + hh];
            dOut[4 * gr + hb + hh] = sm_d[r * 4 + hh];
        }
    }
}

__device__ __forceinline__ void acc8_fp16(float* acc, uint4 v, float ex) {
    float2 f0 = __half22float2(*(__half2*)&v.x);
    float2 f1 = __half22float2(*(__half2*)&v.y);
    float2 f2 = __half22float2(*(__half2*)&v.z);
    float2 f3 = __half22float2(*(__half2*)&v.w);
    acc[0] += ex * f0.x; acc[1] += ex * f0.y;
    acc[2] += ex * f1.x; acc[3] += ex * f1.y;
    acc[4] += ex * f2.x; acc[5] += ex * f2.y;
    acc[6] += ex * f3.x; acc[7] += ex * f3.y;
}

// ---------------- GAT aggregation layer 1 (.cg gathers) ---------------------
__global__ void __launch_bounds__(256) agg1_kernel(
    const float* __restrict__ b1, const float* __restrict__ gm,
    const float* __restrict__ bt, const float* __restrict__ mn,
    const float* __restrict__ vr)
{
    int gw = (blockIdx.x * blockDim.x + threadIdx.x) >> 5;
    if (gw >= NN) return;
    int l = threadIdx.x & 31;
    int start = g_rowptr[gw], end = g_rowptr[gw + 1];
    int head = l >> 3;
    float dh = g_d1[4 * gw + head];
    int c0 = l << 3;
    float acc[8] = {0.f, 0.f, 0.f, 0.f, 0.f, 0.f, 0.f, 0.f};
    float den = 0.f;

    int j = start;
    for (; j + 4 <= end; j += 4) {
        int s0 = g_col[j], s1 = g_col[j + 1], s2 = g_col[j + 2], s3 = g_col[j + 3];
        float e0 = __expf(lrelu(g_s1[4 * s0 + head] + dh));
        float e1 = __expf(lrelu(g_s1[4 * s1 + head] + dh));
        float e2 = __expf(lrelu(g_s1[4 * s2 + head] + dh));
        float e3 = __expf(lrelu(g_s1[4 * s3 + head] + dh));
        uint4 v0 = __ldcg((const uint4*)(g_h1h + (long long)s0 * 256 + c0));
        uint4 v1 = __ldcg((const uint4*)(g_h1h + (long long)s1 * 256 + c0));
        uint4 v2 = __ldcg((const uint4*)(g_h1h + (long long)s2 * 256 + c0));
        uint4 v3 = __ldcg((const uint4*)(g_h1h + (long long)s3 * 256 + c0));
        den += (e0 + e1) + (e2 + e3);
        acc8_fp16(acc, v0, e0);
        acc8_fp16(acc, v1, e1);
        acc8_fp16(acc, v2, e2);
        acc8_fp16(acc, v3, e3);
    }
    for (; j < end; j++) {
        int s = g_col[j];
        float ex = __expf(lrelu(g_s1[4 * s + head] + dh));
        den += ex;
        uint4 v = __ldcg((const uint4*)(g_h1h + (long long)s * 256 + c0));
        acc8_fp16(acc, v, ex);
    }
    float inv = 1.f / (den + 1e-16f);
    float out[8];
#pragma unroll
    for (int i = 0; i < 8; i++) {
        int cc = c0 + i;
        float v = acc[i] * inv + b1[cc];
        v = (v - mn[cc]) * rsqrtf(vr[cc] + EPS_BN) * gm[cc] + bt[cc];
        out[i] = v > 0.f ? v : expm1f(v);
    }
    __half2 q0 = __float22half2_rn(make_float2(out[0], out[1]));
    __half2 q1 = __float22half2_rn(make_float2(out[2], out[3]));
    __half2 q2 = __float22half2_rn(make_float2(out[4], out[5]));
    __half2 q3 = __float22half2_rn(make_float2(out[6], out[7]));
    uint4 wv;
    wv.x = *(unsigned int*)&q0; wv.y = *(unsigned int*)&q1;
    wv.z = *(unsigned int*)&q2; wv.w = *(unsigned int*)&q3;
    *(uint4*)(g_out1h + (long long)gw * 256 + c0) = wv;
}

// ------------ GAT aggregation layer 2 (.cg gathers, BN+ELU+FC) --------------
__global__ void __launch_bounds__(256) agg2_kernel(
    const float* __restrict__ b2, const float* __restrict__ gm,
    const float* __restrict__ bt, const float* __restrict__ mn,
    const float* __restrict__ vr, const float* __restrict__ fcW,
    const float* __restrict__ fcb, float* __restrict__ out)
{
    int gw = (blockIdx.x * blockDim.x + threadIdx.x) >> 5;
    if (gw >= NN) return;
    int l = threadIdx.x & 31;
    int start = g_rowptr[gw], end = g_rowptr[gw + 1];
    int head = l >> 3;
    float dh = g_d2[4 * gw + head];
    int c0 = l << 2;
    float acc[4] = {0.f, 0.f, 0.f, 0.f};
    float den = 0.f;

    int j = start;
    for (; j + 4 <= end; j += 4) {
        int s0 = g_col[j], s1 = g_col[j + 1], s2 = g_col[j + 2], s3 = g_col[j + 3];
        float e0 = __expf(lrelu(g_s2[4 * s0 + head] + dh));
        float e1 = __expf(lrelu(g_s2[4 * s1 + head] + dh));
        float e2 = __expf(lrelu(g_s2[4 * s2 + head] + dh));
        float e3 = __expf(lrelu(g_s2[4 * s3 + head] + dh));
        uint2 v0 = __ldcg((const uint2*)(g_h2h + (long long)s0 * 128 + c0));
        uint2 v1 = __ldcg((const uint2*)(g_h2h + (long long)s1 * 128 + c0));
        uint2 v2 = __ldcg((const uint2*)(g_h2h + (long long)s2 * 128 + c0));
        uint2 v3 = __ldcg((const uint2*)(g_h2h + (long long)s3 * 128 + c0));
        den += (e0 + e1) + (e2 + e3);
        float2 f;
        f = __half22float2(*(__half2*)&v0.x); acc[0] += e0*f.x; acc[1] += e0*f.y;
        f = __half22float2(*(__half2*)&v0.y); acc[2] += e0*f.x; acc[3] += e0*f.y;
        f = __half22float2(*(__half2*)&v1.x); acc[0] += e1*f.x; acc[1] += e1*f.y;
        f = __half22float2(*(__half2*)&v1.y); acc[2] += e1*f.x; acc[3] += e1*f.y;
        f = __half22float2(*(__half2*)&v2.x); acc[0] += e2*f.x; acc[1] += e2*f.y;
        f = __half22float2(*(__half2*)&v2.y); acc[2] += e2*f.x; acc[3] += e2*f.y;
        f = __half22float2(*(__half2*)&v3.x); acc[0] += e3*f.x; acc[1] += e3*f.y;
        f = __half22float2(*(__half2*)&v3.y); acc[2] += e3*f.x; acc[3] += e3*f.y;
    }
    for (; j < end; j++) {
        int s = g_col[j];
        float ex = __expf(lrelu(g_s2[4 * s + head] + dh));
        den += ex;
        uint2 v0 = __ldcg((const uint2*)(g_h2h + (long long)s * 128 + c0));
        float2 f;
        f = __half22float2(*(__half2*)&v0.x); acc[0] += ex*f.x; acc[1] += ex*f.y;
        f = __half22float2(*(__half2*)&v0.y); acc[2] += ex*f.x; acc[3] += ex*f.y;
    }
    float inv = 1.f / (den + 1e-16f);
    float r = 0.f;
#pragma unroll
    for (int i = 0; i < 4; i++) {
        int cc = c0 + i;
        float v = acc[i] * inv + b2[cc];
        v = (v - mn[cc]) * rsqrtf(vr[cc] + EPS_BN) * gm[cc] + bt[cc];
        v = v > 0.f ? v : expm1f(v);
        r += v * fcW[cc];
    }
#pragma unroll
    for (int off = 16; off; off >>= 1) r += __shfl_xor_sync(0xffffffffu, r, off);
    if (l == 0) out[gw] = r + fcb[0];
}

// ---------------- launch ----------------
extern "C" void kernel_launch(void* const* d_in, const int* in_sizes, int n_in,
                              void* d_out, int out_size) {
    const float* x    = (const float*)d_in[0];
    const void*  eidx = d_in[1];
    const float* W1   = (const float*)d_in[2];
    const float* a1s  = (const float*)d_in[3];
    const float* a1d  = (const float*)d_in[4];
    const float* b1   = (const float*)d_in[5];
    const float* g1   = (const float*)d_in[6];
    const float* be1  = (const float*)d_in[7];
    const float* m1   = (const float*)d_in[8];
    const float* v1   = (const float*)d_in[9];
    const float* W2   = (const float*)d_in[10];
    const float* a2s  = (const float*)d_in[11];
    const float* a2d  = (const float*)d_in[12];
    const float* b2   = (const float*)d_in[13];
    const float* g2   = (const float*)d_in[14];
    const float* be2  = (const float*)d_in[15];
    const float* m2   = (const float*)d_in[16];
    const float* v2   = (const float*)d_in[17];
    const float* fcW  = (const float*)d_in[18];
    const float* fcb  = (const float*)d_in[19];

    int E  = in_sizes[1] / 2;
    int EP = E + NN;

    int smem_bytes = (3 * AS_STAGE + 3 * BS_STAGE) * 2 + 1024 * 4;
    cudaFuncSetAttribute(gemm_kernel,
        cudaFuncAttributeMaxDynamicSharedMemorySize, smem_bytes);
    cudaFuncSetAttribute(gemm_kernel,
        cudaFuncAttributePreferredSharedMemoryCarveout, 100);

    static cudaStream_t s_side = 0;
    static cudaEvent_t  s_fork = 0, s_join = 0;
    if (!s_side) {
        cudaStreamCreateWithFlags(&s_side, cudaStreamNonBlocking);
        cudaEventCreateWithFlags(&s_fork, cudaEventDisableTiming);
        cudaEventCreateWithFlags(&s_join, cudaEventDisableTiming);
    }

    float *s1p, *d1p, *s2p, *d2p;
    __half *h1hp, *h2hp, *out1hp, *xhp, *w1hp, *w2hp;
    cudaGetSymbolAddress((void**)&h1hp,   g_h1h);
    cudaGetSymbolAddress((void**)&h2hp,   g_h2h);
    cudaGetSymbolAddress((void**)&out1hp, g_out1h);
    cudaGetSymbolAddress((void**)&xhp,    g_xh);
    cudaGetSymbolAddress((void**)&w1hp,   g_w1h);
    cudaGetSymbolAddress((void**)&w2hp,   g_w2h);
    cudaGetSymbolAddress((void**)&s1p,    g_s1);
    cudaGetSymbolAddress((void**)&d1p,    g_d1);
    cudaGetSymbolAddress((void**)&s2p,    g_s2);
    cudaGetSymbolAddress((void**)&d2p,    g_d2);

    const int TPB = 256;
    int warp_blocks = (NN * 32 + TPB - 1) / TPB;
    int f2h_blocks  = (NN * 128 / 4 + 2 * (128 * 256 / 4) + 255) / 256;

    // fork: CSR build (side) concurrent with f2h+gemm1 (main)
    cudaEventRecord(s_fork, 0);
    cudaStreamWaitEvent(s_side, s_fork, 0);
    csr_kernel<<<CSR_NBLK, 1024, 0, s_side>>>(eidx, E, EP);
    cudaEventRecord(s_join, s_side);

    f2h_all_kernel<<<f2h_blocks, 256>>>(x, W1, W2);
    gemm_kernel<<<dim3(2, (NN + 127) / 128), 256, smem_bytes>>>(
        xhp, w1hp, h1hp, a1s, a1d, s1p, d1p, NN, 128, 256, 6);

    // agg1 (after CSR join) <- profiled slot 4
    cudaStreamWaitEvent(0, s_join, 0);
    agg1_kernel<<<warp_blocks, TPB>>>(b1, g1, be1, m1, v1);

    gemm_kernel<<<dim3(1, (NN + 127) / 128), 256, smem_bytes>>>(
        out1hp, w2hp, h2hp, a2s, a2d, s2p, d2p, NN, 256, 128, 5);
    agg2_kernel<<<warp_blocks, TPB>>>(b2, g2, be2, m2, v2, fcW, fcb, (float*)d_out);
}